// round 7
// baseline (speedup 1.0000x reference)
#include <cuda_runtime.h>
#include <math.h>

#define NB   4
#define NN   16384
#define ND   256
#define NK   16
#define NSD  64
#define NH   128
#define NW   128
#define MTOT (NB*NN)          // 65536 rows
#define BIG_NEG -10000.0f

// ---------------- scratch (no allocations allowed) ----------------
__device__ float g_q  [(size_t)MTOT*ND];
__device__ float g_k  [(size_t)MTOT*ND];
__device__ float g_v  [(size_t)MTOT*ND];
__device__ float g_agg[(size_t)MTOT*ND];
__device__ float g_Anorm[MTOT];
__device__ float g_red[2];     // [0]=dy sum, [1]=dx sum

// ---------------- helpers ----------------
__device__ __forceinline__ float gelu_f(float x){
    return 0.5f * x * (1.0f + erff(x * 0.70710678118654752f));
}
__device__ __forceinline__ unsigned long long pack2(float lo, float hi){
    unsigned long long r;
    asm("mov.b64 %0, {%1, %2};" : "=l"(r) : "f"(lo), "f"(hi));
    return r;
}
__device__ __forceinline__ void unpack2(unsigned long long x, float &lo, float &hi){
    asm("mov.b64 {%0, %1}, %2;" : "=f"(lo), "=f"(hi) : "l"(x));
}
__device__ __forceinline__ void ffma2(unsigned long long &d,
                                      unsigned long long a,
                                      unsigned long long b){
    asm("fma.rn.f32x2 %0, %1, %2, %3;" : "=l"(d) : "l"(a), "l"(b), "l"(d));
}

// ---------------- GEMM: C[M,256] = A[M,256] @ W[256,256] + bias ----------------
// mode 0: plain store.  mode 1: h = Zres + C; LayerNorm(h) -> C.
// BM=64, BN=256 (full row per block), BK=8, 256 threads, 8x8 per thread,
// packed f32x2 FMA inner loop.
__global__ __launch_bounds__(256) void sgemm_k(
    const float* __restrict__ A, const float* __restrict__ W,
    const float* __restrict__ bias, float* __restrict__ C,
    const float* __restrict__ Zres, const float* __restrict__ lng,
    const float* __restrict__ lnb, int mode)
{
    __shared__ __align__(16) float As[8][64];
    __shared__ __align__(16) float Bs[8][256];
    const int tid = threadIdx.x;
    const int tx = tid & 31, ty = tid >> 5;
    const int m0 = blockIdx.x * 64;

    unsigned long long acc[8][4];
    #pragma unroll
    for (int i = 0; i < 8; i++)
        #pragma unroll
        for (int p = 0; p < 4; p++) acc[i][p] = 0ULL;

    for (int k0 = 0; k0 < 256; k0 += 8) {
        if (tid < 128) {
            int row = tid >> 1, cg = tid & 1;
            float4 av = *(const float4*)(A + (size_t)(m0 + row)*256 + k0 + cg*4);
            As[cg*4+0][row] = av.x; As[cg*4+1][row] = av.y;
            As[cg*4+2][row] = av.z; As[cg*4+3][row] = av.w;
        }
        #pragma unroll
        for (int r = 0; r < 2; r++) {
            int f = tid + 256*r;
            int rowb = f >> 6, c4 = f & 63;
            *(float4*)(&Bs[rowb][c4*4]) =
                *(const float4*)(W + (size_t)(k0 + rowb)*256 + c4*4);
        }
        __syncthreads();
        #pragma unroll
        for (int kk = 0; kk < 8; kk++) {
            float4 a0 = *(const float4*)(&As[kk][ty*8]);
            float4 a1 = *(const float4*)(&As[kk][ty*8+4]);
            unsigned long long ad[8];
            ad[0]=pack2(a0.x,a0.x); ad[1]=pack2(a0.y,a0.y);
            ad[2]=pack2(a0.z,a0.z); ad[3]=pack2(a0.w,a0.w);
            ad[4]=pack2(a1.x,a1.x); ad[5]=pack2(a1.y,a1.y);
            ad[6]=pack2(a1.z,a1.z); ad[7]=pack2(a1.w,a1.w);
            unsigned long long b2[4];
            #pragma unroll
            for (int p = 0; p < 4; p++)
                b2[p] = *(const unsigned long long*)(&Bs[kk][tx*8 + p*2]);
            #pragma unroll
            for (int i = 0; i < 8; i++)
                #pragma unroll
                for (int p = 0; p < 4; p++)
                    ffma2(acc[i][p], ad[i], b2[p]);
        }
        __syncthreads();
    }

    const int col0 = tx*8;
    if (mode == 0) {
        float bv[8];
        #pragma unroll
        for (int j = 0; j < 8; j++) bv[j] = bias[col0+j];
        #pragma unroll
        for (int i = 0; i < 8; i++) {
            size_t row = (size_t)m0 + ty*8 + i;
            float v[8];
            #pragma unroll
            for (int p = 0; p < 4; p++) unpack2(acc[i][p], v[2*p], v[2*p+1]);
            *(float4*)(C + row*256 + col0) =
                make_float4(v[0]+bv[0], v[1]+bv[1], v[2]+bv[2], v[3]+bv[3]);
            *(float4*)(C + row*256 + col0 + 4) =
                make_float4(v[4]+bv[4], v[5]+bv[5], v[6]+bv[6], v[7]+bv[7]);
        }
    } else {
        float bv[8], gv[8], bb[8];
        #pragma unroll
        for (int j = 0; j < 8; j++) {
            bv[j] = bias[col0+j]; gv[j] = lng[col0+j]; bb[j] = lnb[col0+j];
        }
        #pragma unroll
        for (int i = 0; i < 8; i++) {
            size_t row = (size_t)m0 + ty*8 + i;
            float v[8];
            #pragma unroll
            for (int p = 0; p < 4; p++) unpack2(acc[i][p], v[2*p], v[2*p+1]);
            float4 z0 = *(const float4*)(Zres + row*256 + col0);
            float4 z1 = *(const float4*)(Zres + row*256 + col0 + 4);
            v[0]+=bv[0]+z0.x; v[1]+=bv[1]+z0.y; v[2]+=bv[2]+z0.z; v[3]+=bv[3]+z0.w;
            v[4]+=bv[4]+z1.x; v[5]+=bv[5]+z1.y; v[6]+=bv[6]+z1.z; v[7]+=bv[7]+z1.w;
            float s1 = 0.f, s2 = 0.f;
            #pragma unroll
            for (int j = 0; j < 8; j++) { s1 += v[j]; s2 += v[j]*v[j]; }
            #pragma unroll
            for (int off = 16; off; off >>= 1) {
                s1 += __shfl_xor_sync(0xffffffffu, s1, off);
                s2 += __shfl_xor_sync(0xffffffffu, s2, off);
            }
            float mean = s1 * (1.f/256.f);
            float var  = s2 * (1.f/256.f) - mean*mean;
            float rstd = rsqrtf(var + 1e-5f);
            float o[8];
            #pragma unroll
            for (int j = 0; j < 8; j++)
                o[j] = gv[j]*(v[j]-mean)*rstd + bb[j];
            *(float4*)(C + row*256 + col0) = make_float4(o[0],o[1],o[2],o[3]);
            *(float4*)(C + row*256 + col0+4) = make_float4(o[4],o[5],o[6],o[7]);
        }
    }
}

// ---------------- attention: one block per (b,n), 256 threads ----------------
__global__ __launch_bounds__(256) void attn_kernel(
    const float* __restrict__ z,   const float* __restrict__ S,
    const float* __restrict__ rel, const float* __restrict__ geod,
    const int*   __restrict__ idx,
    const float* __restrict__ Wzg, const float* __restrict__ bzg,
    const float* __restrict__ Ws1, const float* __restrict__ bs1,
    const float* __restrict__ Ws2, const float* __restrict__ bs2,
    const float* __restrict__ Wph, const float* __restrict__ bph,
    const float* __restrict__ Wsg, const float* __restrict__ bsg)
{
    const int n = blockIdx.x, b = blockIdx.y;
    const int t = threadIdx.x;
    __shared__ float q_row[256], z_row[256], S_row[64];
    __shared__ float ker[32];
    __shared__ float sA00, sA01, sA11, sg[3];
    __shared__ float logits[16], att[16];
    __shared__ int   nbs[16];
    __shared__ float vsm[16][256];

    const size_t node = (size_t)b*NN + n;
    q_row[t] = g_q[node*256 + t];
    z_row[t] = z  [node*256 + t];
    if (t < 64) S_row[t] = S[node*64 + t];
    if (t < 16) nbs[t] = idx[n*16 + t];
    __syncthreads();

    // z_emb: 16 outputs, 16 threads each (width-16 shfl reduce)
    {
        int c = t >> 4, g = t & 15;
        float p = 0.f;
        #pragma unroll
        for (int i = 0; i < 16; i++) {
            int d = g*16 + i;
            p = fmaf(z_row[d], Wzg[d*16 + c], p);
        }
        #pragma unroll
        for (int off = 8; off; off >>= 1)
            p += __shfl_down_sync(0xffffffffu, p, off, 16);
        if (g == 0) ker[16 + c] = gelu_f(p + bzg[c]);
    }
    // m1,m2 + s_emb (warp 0; tiny)
    if (t < 32) {
        float a0 = S_row[t], a1 = S_row[t+32];
        float s1 = a0 + a1;
        float s2 = a0*a0 + a1*a1;
        #pragma unroll
        for (int off = 16; off; off >>= 1) {
            s1 += __shfl_down_sync(0xffffffffu, s1, off);
            s2 += __shfl_down_sync(0xffffffffu, s2, off);
        }
        if (t == 0) {
            float m1 = s1 * (1.f/64.f), m2 = s2 * (1.f/64.f);
            float h1[16];
            #pragma unroll
            for (int c = 0; c < 16; c++)
                h1[c] = gelu_f(fmaf(m1, Ws1[c], fmaf(m2, Ws1[16+c], bs1[c])));
            #pragma unroll
            for (int c = 0; c < 16; c++) {
                float a = bs2[c];
                #pragma unroll
                for (int i = 0; i < 16; i++) a = fmaf(h1[i], Ws2[i*16+c], a);
                ker[c] = gelu_f(a);
            }
        }
    }
    __syncthreads();

    // abc, A-matrix, gate softmax, A_norm (thread 0)
    if (t == 0) {
        float abc[3], sl[3];
        #pragma unroll
        for (int c = 0; c < 3; c++) {
            float a = bph[c], s = bsg[c];
            #pragma unroll
            for (int i = 0; i < 32; i++) {
                a = fmaf(ker[i], Wph[i*3+c], a);
                s = fmaf(ker[i], Wsg[i*3+c], s);
            }
            abc[c] = a; sl[c] = s;
        }
        float La = expf(abc[0]), Lb = abc[1], Lc = expf(abc[2]);
        float A00 = La*La, A01 = La*Lb, A11 = Lb*Lb + Lc*Lc;
        sA00 = A00; sA01 = A01; sA11 = A11;
        g_Anorm[node] = sqrtf(A00*A00 + 2.f*A01*A01 + A11*A11);
        float mx = fmaxf(sl[0], fmaxf(sl[1], sl[2]));
        float e0 = expf(sl[0]-mx), e1 = expf(sl[1]-mx), e2 = expf(sl[2]-mx);
        float inv = 1.f/(e0+e1+e2);
        sg[0] = e0*inv; sg[1] = e1*inv; sg[2] = e2*inv;
    }
    __syncthreads();

    // content + sim per neighbor; stage v rows in smem
    {
        int j = t >> 4, g = t & 15;
        int nb = nbs[j];
        size_t kb = ((size_t)b*NN + nb) * 256;
        const float* __restrict__ krow = g_k + kb;
        const float* __restrict__ vrow = g_v + kb;
        float c = 0.f;
        #pragma unroll
        for (int i = 0; i < 16; i++) {
            int d = g + 16*i;
            c = fmaf(q_row[d], krow[d], c);
            vsm[j][d] = vrow[d];
        }
        const float* __restrict__ srow = S + ((size_t)b*NN + nb)*64;
        float sm = 0.f;
        #pragma unroll
        for (int i = 0; i < 4; i++) {
            int d = g + 16*i;
            sm = fmaf(S_row[d], srow[d], sm);
        }
        #pragma unroll
        for (int off = 8; off; off >>= 1) {
            c  += __shfl_down_sync(0xffffffffu, c,  off, 16);
            sm += __shfl_down_sync(0xffffffffu, sm, off, 16);
        }
        if (g == 0) {
            float gd = geod[n*16 + j];
            float r0 = rel[(n*16 + j)*2 + 0];
            float r1 = rel[(n*16 + j)*2 + 1];
            float rAr = sA00*r0*r0 + 2.f*sA01*r0*r1 + sA11*r1*r1;
            float center = expf(-gd*gd * (1.f/2.25f));
            float common = c * 0.0625f + sm - 0.25f*gd;
            float extra = 0.f;
            {   float s = fmaf(0.20f, gd, 0.25f); float s2 = fmaxf(s*s, 1e-6f);
                float m = (gd > 1.5f) ? BIG_NEG : 0.f;
                extra += sg[0]*(-rAr/s2 + 0.7f*center + m); }
            {   float s = fmaf(0.20f, gd, 0.35f); float s2 = fmaxf(s*s, 1e-6f);
                float m = (gd > 2.5f) ? BIG_NEG : 0.f;
                extra += sg[1]*(-rAr/s2 + 0.5f*center + m); }
            {   float s = fmaf(0.25f, gd, 0.55f); float s2 = fmaxf(s*s, 1e-6f);
                float m = (gd > 4.0f) ? BIG_NEG : 0.f;
                extra += sg[2]*(-rAr/s2 + 0.3f*center + m); }
            logits[j] = common + extra;
        }
    }
    __syncthreads();

    if (t == 0) {
        float mx = -1e30f;
        #pragma unroll
        for (int j = 0; j < 16; j++) mx = fmaxf(mx, logits[j]);
        float s = 0.f;
        #pragma unroll
        for (int j = 0; j < 16; j++) { float e = expf(logits[j]-mx); att[j] = e; s += e; }
        float inv = 1.f/s;
        #pragma unroll
        for (int j = 0; j < 16; j++) att[j] *= inv;
    }
    __syncthreads();

    {   // aggregate: thread t = dim d
        float a = 0.f;
        #pragma unroll
        for (int j = 0; j < 16; j++) a = fmaf(att[j], vsm[j][t], a);
        g_agg[node*256 + t] = a;
    }
}

// ---------------- TV regularizer ----------------
__global__ void zero_red_kernel() { g_red[0] = 0.f; g_red[1] = 0.f; }

__global__ void tv_kernel() {
    int i = blockIdx.x*blockDim.x + threadIdx.x;   // 0..65535
    int p = i & (NN-1);
    int r = p >> 7, cc = p & (NW-1);
    float a = g_Anorm[i];
    float dy = (r  < NH-1) ? fabsf(g_Anorm[i+NW] - a) : 0.f;
    float dx = (cc < NW-1) ? fabsf(g_Anorm[i+1]  - a) : 0.f;
    #pragma unroll
    for (int off = 16; off; off >>= 1) {
        dy += __shfl_xor_sync(0xffffffffu, dy, off);
        dx += __shfl_xor_sync(0xffffffffu, dx, off);
    }
    if ((threadIdx.x & 31) == 0) {
        atomicAdd(&g_red[0], dy);
        atomicAdd(&g_red[1], dx);
    }
}

__global__ void fin_kernel(float* out, int pos) {
    // dy mean over B*(H-1)*W = 65024; dx mean over B*H*(W-1) = 65024
    out[pos] = 0.001f * (g_red[1]*(1.0f/65024.f) + g_red[0]*(1.0f/65024.f));
}

// ---------------- launch ----------------
extern "C" void kernel_launch(void* const* d_in, const int* in_sizes, int n_in,
                              void* d_out, int out_size)
{
    (void)in_sizes; (void)n_in;
    const float* z   = (const float*)d_in[0];
    const float* S   = (const float*)d_in[1];
    const float* rel = (const float*)d_in[2];
    const float* geod= (const float*)d_in[3];
    const int*   idx = (const int*)  d_in[4];
    const float* Wq  = (const float*)d_in[5];
    const float* bq  = (const float*)d_in[6];
    const float* Wk  = (const float*)d_in[7];
    const float* bk  = (const float*)d_in[8];
    const float* Wv  = (const float*)d_in[9];
    const float* bv  = (const float*)d_in[10];
    const float* Wo  = (const float*)d_in[11];
    const float* bo  = (const float*)d_in[12];
    const float* lng = (const float*)d_in[13];
    const float* lnb = (const float*)d_in[14];
    const float* Ws1 = (const float*)d_in[15];
    const float* bs1 = (const float*)d_in[16];
    const float* Ws2 = (const float*)d_in[17];
    const float* bs2 = (const float*)d_in[18];
    const float* Wzg = (const float*)d_in[19];
    const float* bzg = (const float*)d_in[20];
    const float* Wph = (const float*)d_in[21];
    const float* bph = (const float*)d_in[22];
    const float* Wsg = (const float*)d_in[23];
    const float* bsg = (const float*)d_in[24];
    float* out = (float*)d_out;

    float *pq, *pk, *pv, *pagg;
    cudaGetSymbolAddress((void**)&pq,   g_q);
    cudaGetSymbolAddress((void**)&pk,   g_k);
    cudaGetSymbolAddress((void**)&pv,   g_v);
    cudaGetSymbolAddress((void**)&pagg, g_agg);

    dim3 gg(MTOT/64);
    sgemm_k<<<gg, 256>>>(z, Wq, bq, pq, nullptr, nullptr, nullptr, 0);
    sgemm_k<<<gg, 256>>>(z, Wk, bk, pk, nullptr, nullptr, nullptr, 0);
    sgemm_k<<<gg, 256>>>(z, Wv, bv, pv, nullptr, nullptr, nullptr, 0);

    dim3 ga(NN, NB);
    attn_kernel<<<ga, 256>>>(z, S, rel, geod, idx,
                             Wzg, bzg, Ws1, bs1, Ws2, bs2,
                             Wph, bph, Wsg, bsg);

    sgemm_k<<<gg, 256>>>(pagg, Wo, bo, out, z, lng, lnb, 1);

    zero_red_kernel<<<1, 1>>>();
    tv_kernel<<<256, 256>>>();
    fin_kernel<<<1, 1>>>(out, out_size - 1);
}

// round 8
// speedup vs baseline: 1.8184x; 1.8184x over previous
#include <cuda_runtime.h>
#include <math.h>

#define NB   4
#define NN   16384
#define ND   256
#define NK   16
#define NSD  64
#define NH   128
#define NW   128
#define MTOT (NB*NN)          // 65536 rows
#define BIG_NEG -10000.0f

// ---------------- scratch (no allocations allowed) ----------------
__device__ float g_q  [(size_t)MTOT*ND];
__device__ float g_k  [(size_t)MTOT*ND];
__device__ float g_v  [(size_t)MTOT*ND];
__device__ float g_agg[(size_t)MTOT*ND];
__device__ float g_par[(size_t)MTOT*8];   // A00,A01,A11,g0,g1,g2
__device__ float g_Anorm[MTOT];
__device__ float g_red[2];     // [0]=dy sum, [1]=dx sum

// ---------------- helpers ----------------
__device__ __forceinline__ float gelu_f(float x){
    return 0.5f * x * (1.0f + erff(x * 0.70710678118654752f));
}
__device__ __forceinline__ unsigned long long pack2(float lo, float hi){
    unsigned long long r;
    asm("mov.b64 %0, {%1, %2};" : "=l"(r) : "f"(lo), "f"(hi));
    return r;
}
__device__ __forceinline__ void unpack2(unsigned long long x, float &lo, float &hi){
    asm("mov.b64 {%0, %1}, %2;" : "=f"(lo), "=f"(hi) : "l"(x));
}
__device__ __forceinline__ void ffma2(unsigned long long &d,
                                      unsigned long long a,
                                      unsigned long long b){
    asm("fma.rn.f32x2 %0, %1, %2, %3;" : "=l"(d) : "l"(a), "l"(b), "l"(d));
}

// ---------------- GEMM: C[M,256] = A[M,256] @ W[256,256] + bias ----------------
// mode 0: plain store.  mode 1: h = Zres + C; LayerNorm(h) -> C.
__global__ __launch_bounds__(256) void sgemm_k(
    const float* __restrict__ A, const float* __restrict__ W,
    const float* __restrict__ bias, float* __restrict__ C,
    const float* __restrict__ Zres, const float* __restrict__ lng,
    const float* __restrict__ lnb, int mode)
{
    __shared__ __align__(16) float As[8][64];
    __shared__ __align__(16) float Bs[8][256];
    const int tid = threadIdx.x;
    const int tx = tid & 31, ty = tid >> 5;
    const int m0 = blockIdx.x * 64;

    unsigned long long acc[8][4];
    #pragma unroll
    for (int i = 0; i < 8; i++)
        #pragma unroll
        for (int p = 0; p < 4; p++) acc[i][p] = 0ULL;

    for (int k0 = 0; k0 < 256; k0 += 8) {
        if (tid < 128) {
            int row = tid >> 1, cg = tid & 1;
            float4 av = *(const float4*)(A + (size_t)(m0 + row)*256 + k0 + cg*4);
            As[cg*4+0][row] = av.x; As[cg*4+1][row] = av.y;
            As[cg*4+2][row] = av.z; As[cg*4+3][row] = av.w;
        }
        #pragma unroll
        for (int r = 0; r < 2; r++) {
            int f = tid + 256*r;
            int rowb = f >> 6, c4 = f & 63;
            *(float4*)(&Bs[rowb][c4*4]) =
                *(const float4*)(W + (size_t)(k0 + rowb)*256 + c4*4);
        }
        __syncthreads();
        #pragma unroll
        for (int kk = 0; kk < 8; kk++) {
            float4 a0 = *(const float4*)(&As[kk][ty*8]);
            float4 a1 = *(const float4*)(&As[kk][ty*8+4]);
            unsigned long long ad[8];
            ad[0]=pack2(a0.x,a0.x); ad[1]=pack2(a0.y,a0.y);
            ad[2]=pack2(a0.z,a0.z); ad[3]=pack2(a0.w,a0.w);
            ad[4]=pack2(a1.x,a1.x); ad[5]=pack2(a1.y,a1.y);
            ad[6]=pack2(a1.z,a1.z); ad[7]=pack2(a1.w,a1.w);
            unsigned long long b2[4];
            #pragma unroll
            for (int p = 0; p < 4; p++)
                b2[p] = *(const unsigned long long*)(&Bs[kk][tx*8 + p*2]);
            #pragma unroll
            for (int i = 0; i < 8; i++)
                #pragma unroll
                for (int p = 0; p < 4; p++)
                    ffma2(acc[i][p], ad[i], b2[p]);
        }
        __syncthreads();
    }

    const int col0 = tx*8;
    if (mode == 0) {
        float bv[8];
        #pragma unroll
        for (int j = 0; j < 8; j++) bv[j] = bias[col0+j];
        #pragma unroll
        for (int i = 0; i < 8; i++) {
            size_t row = (size_t)m0 + ty*8 + i;
            float v[8];
            #pragma unroll
            for (int p = 0; p < 4; p++) unpack2(acc[i][p], v[2*p], v[2*p+1]);
            *(float4*)(C + row*256 + col0) =
                make_float4(v[0]+bv[0], v[1]+bv[1], v[2]+bv[2], v[3]+bv[3]);
            *(float4*)(C + row*256 + col0 + 4) =
                make_float4(v[4]+bv[4], v[5]+bv[5], v[6]+bv[6], v[7]+bv[7]);
        }
    } else {
        float bv[8], gv[8], bb[8];
        #pragma unroll
        for (int j = 0; j < 8; j++) {
            bv[j] = bias[col0+j]; gv[j] = lng[col0+j]; bb[j] = lnb[col0+j];
        }
        #pragma unroll
        for (int i = 0; i < 8; i++) {
            size_t row = (size_t)m0 + ty*8 + i;
            float v[8];
            #pragma unroll
            for (int p = 0; p < 4; p++) unpack2(acc[i][p], v[2*p], v[2*p+1]);
            float4 z0 = *(const float4*)(Zres + row*256 + col0);
            float4 z1 = *(const float4*)(Zres + row*256 + col0 + 4);
            v[0]+=bv[0]+z0.x; v[1]+=bv[1]+z0.y; v[2]+=bv[2]+z0.z; v[3]+=bv[3]+z0.w;
            v[4]+=bv[4]+z1.x; v[5]+=bv[5]+z1.y; v[6]+=bv[6]+z1.z; v[7]+=bv[7]+z1.w;
            float s1 = 0.f, s2 = 0.f;
            #pragma unroll
            for (int j = 0; j < 8; j++) { s1 += v[j]; s2 += v[j]*v[j]; }
            #pragma unroll
            for (int off = 16; off; off >>= 1) {
                s1 += __shfl_xor_sync(0xffffffffu, s1, off);
                s2 += __shfl_xor_sync(0xffffffffu, s2, off);
            }
            float mean = s1 * (1.f/256.f);
            float var  = s2 * (1.f/256.f) - mean*mean;
            float rstd = rsqrtf(var + 1e-5f);
            float o[8];
            #pragma unroll
            for (int j = 0; j < 8; j++)
                o[j] = gv[j]*(v[j]-mean)*rstd + bb[j];
            *(float4*)(C + row*256 + col0) = make_float4(o[0],o[1],o[2],o[3]);
            *(float4*)(C + row*256 + col0+4) = make_float4(o[4],o[5],o[6],o[7]);
        }
    }
}

// ---------------- per-node kernel params: one thread per node ----------------
// Computes s_emb, z_emb, abc -> (A00,A01,A11), gate softmax, A_norm.
// Wzg staged in smem and read UNIFORMLY across the warp (broadcast, no
// strided-sector wavefront storm).
__global__ __launch_bounds__(256) void param_kernel(
    const float* __restrict__ z,   const float* __restrict__ S,
    const float* __restrict__ Wzg, const float* __restrict__ bzg,
    const float* __restrict__ Ws1, const float* __restrict__ bs1,
    const float* __restrict__ Ws2, const float* __restrict__ bs2,
    const float* __restrict__ Wph, const float* __restrict__ bph,
    const float* __restrict__ Wsg, const float* __restrict__ bsg)
{
    __shared__ __align__(16) float sWzg[4096];   // 256 x 16
    __shared__ float sWs1[32], sbs1[16], sWs2[256], sbs2[16], sbzg[16];
    __shared__ float sWph[96], sbph[3], sWsg[96], sbsg[3];

    const int t = threadIdx.x;
    #pragma unroll
    for (int r = 0; r < 4; r++)
        ((float4*)sWzg)[t + 256*r] = ((const float4*)Wzg)[t + 256*r];
    if (t < 32)  sWs1[t] = Ws1[t];
    if (t < 16) { sbs1[t] = bs1[t]; sbs2[t] = bs2[t]; sbzg[t] = bzg[t]; }
    if (t < 256) sWs2[t] = Ws2[t];
    if (t < 96) { sWph[t] = Wph[t]; sWsg[t] = Wsg[t]; }
    if (t < 3)  { sbph[t] = bph[t]; sbsg[t] = bsg[t]; }
    __syncthreads();

    const size_t node = (size_t)blockIdx.x * 256 + t;

    // S stats
    const float4* s4 = (const float4*)(S + node*64);
    float s1 = 0.f, s2 = 0.f;
    #pragma unroll
    for (int i = 0; i < 16; i++) {
        float4 v = s4[i];
        s1 += v.x + v.y + v.z + v.w;
        s2 += v.x*v.x + v.y*v.y + v.z*v.z + v.w*v.w;
    }
    float m1 = s1 * (1.f/64.f), m2 = s2 * (1.f/64.f);

    // s_emb
    float h1[16];
    #pragma unroll
    for (int c = 0; c < 16; c++)
        h1[c] = gelu_f(fmaf(m1, sWs1[c], fmaf(m2, sWs1[16+c], sbs1[c])));
    float ker[32];
    #pragma unroll
    for (int c = 0; c < 16; c++) {
        float a = sbs2[c];
        #pragma unroll
        for (int i = 0; i < 16; i++) a = fmaf(h1[i], sWs2[i*16+c], a);
        ker[c] = gelu_f(a);
    }

    // z_emb: uniform smem weight reads (broadcast)
    float acc[16];
    #pragma unroll
    for (int c = 0; c < 16; c++) acc[c] = sbzg[c];
    const float4* z4 = (const float4*)(z + node*256);
    for (int i4 = 0; i4 < 64; i4++) {
        float4 zv = z4[i4];
        const float* w = &sWzg[i4*64];
        #pragma unroll
        for (int c = 0; c < 16; c++) {
            acc[c] = fmaf(zv.x, w[c],      acc[c]);
            acc[c] = fmaf(zv.y, w[16+c],   acc[c]);
            acc[c] = fmaf(zv.z, w[32+c],   acc[c]);
            acc[c] = fmaf(zv.w, w[48+c],   acc[c]);
        }
    }
    #pragma unroll
    for (int c = 0; c < 16; c++) ker[16+c] = gelu_f(acc[c]);

    // abc + gate logits
    float abc[3], sl[3];
    #pragma unroll
    for (int c = 0; c < 3; c++) {
        float a = sbph[c], s = sbsg[c];
        #pragma unroll
        for (int i = 0; i < 32; i++) {
            a = fmaf(ker[i], sWph[i*3+c], a);
            s = fmaf(ker[i], sWsg[i*3+c], s);
        }
        abc[c] = a; sl[c] = s;
    }
    float La = expf(abc[0]), Lb = abc[1], Lc = expf(abc[2]);
    float A00 = La*La, A01 = La*Lb, A11 = Lb*Lb + Lc*Lc;
    g_Anorm[node] = sqrtf(A00*A00 + 2.f*A01*A01 + A11*A11);
    float mx = fmaxf(sl[0], fmaxf(sl[1], sl[2]));
    float e0 = expf(sl[0]-mx), e1 = expf(sl[1]-mx), e2 = expf(sl[2]-mx);
    float inv = 1.f/(e0+e1+e2);

    float* p = g_par + node*8;
    p[0] = A00; p[1] = A01; p[2] = A11;
    p[3] = e0*inv; p[4] = e1*inv; p[5] = e2*inv;
}

// ---------------- attention: one block per (b,n), 256 threads, all float4 ----
__global__ __launch_bounds__(256) void attn_kernel(
    const float* __restrict__ S,
    const float* __restrict__ rel, const float* __restrict__ geod,
    const int*   __restrict__ idx)
{
    const int n = blockIdx.x, b = blockIdx.y;
    const int t = threadIdx.x;
    __shared__ __align__(16) float4 q4[64];
    __shared__ __align__(16) float4 S4[16];
    __shared__ float logits[16], att_s[16], par[6];
    __shared__ int   nbs[16];

    const size_t node = (size_t)b*NN + n;
    if (t < 64)               q4[t]       = ((const float4*)(g_q + node*256))[t];
    else if (t < 80)          S4[t-64]    = ((const float4*)(S + node*64))[t-64];
    else if (t >= 96 && t < 112) nbs[t-96] = idx[n*16 + (t-96)];
    else if (t >= 112 && t < 118) par[t-112] = g_par[node*8 + (t-112)];
    __syncthreads();

    // content + sim per neighbor: 16 groups x 16 threads, float4 loads
    {
        const int j = t >> 4, g = t & 15;
        const int nb = nbs[j];
        const float4* __restrict__ k4 =
            (const float4*)(g_k + ((size_t)b*NN + nb)*256);
        float c = 0.f;
        #pragma unroll
        for (int ii = 0; ii < 4; ii++) {
            float4 a = q4[g + 16*ii];
            float4 kk = k4[g + 16*ii];
            c = fmaf(a.x, kk.x, c); c = fmaf(a.y, kk.y, c);
            c = fmaf(a.z, kk.z, c); c = fmaf(a.w, kk.w, c);
        }
        const float4* __restrict__ sn4 =
            (const float4*)(S + ((size_t)b*NN + nb)*64);
        float4 sa = S4[g], sb = sn4[g];
        float sm = sa.x*sb.x + sa.y*sb.y + sa.z*sb.z + sa.w*sb.w;
        #pragma unroll
        for (int off = 8; off; off >>= 1) {
            c  += __shfl_down_sync(0xffffffffu, c,  off, 16);
            sm += __shfl_down_sync(0xffffffffu, sm, off, 16);
        }
        if (g == 0) {
            float gd = geod[n*16 + j];
            float r0 = rel[(n*16 + j)*2 + 0];
            float r1 = rel[(n*16 + j)*2 + 1];
            float A00 = par[0], A01 = par[1], A11 = par[2];
            float rAr = A00*r0*r0 + 2.f*A01*r0*r1 + A11*r1*r1;
            float center = expf(-gd*gd * (1.f/2.25f));
            float common = c * 0.0625f + sm - 0.25f*gd;
            float extra = 0.f;
            {   float s = fmaf(0.20f, gd, 0.25f); float s2 = fmaxf(s*s, 1e-6f);
                float m = (gd > 1.5f) ? BIG_NEG : 0.f;
                extra += par[3]*(-rAr/s2 + 0.7f*center + m); }
            {   float s = fmaf(0.20f, gd, 0.35f); float s2 = fmaxf(s*s, 1e-6f);
                float m = (gd > 2.5f) ? BIG_NEG : 0.f;
                extra += par[4]*(-rAr/s2 + 0.5f*center + m); }
            {   float s = fmaf(0.25f, gd, 0.55f); float s2 = fmaxf(s*s, 1e-6f);
                float m = (gd > 4.0f) ? BIG_NEG : 0.f;
                extra += par[5]*(-rAr/s2 + 0.3f*center + m); }
            logits[j] = common + extra;
        }
    }
    __syncthreads();

    if (t == 0) {
        float mx = -1e30f;
        #pragma unroll
        for (int j = 0; j < 16; j++) mx = fmaxf(mx, logits[j]);
        float s = 0.f;
        #pragma unroll
        for (int j = 0; j < 16; j++) { float e = expf(logits[j]-mx); att_s[j] = e; s += e; }
        float inv = 1.f/s;
        #pragma unroll
        for (int j = 0; j < 16; j++) att_s[j] *= inv;
    }
    __syncthreads();

    // aggregate: 64 threads, each owns one float4 output chunk, reads v
    // rows directly from global (L2-resident due to neighbor reuse)
    if (t < 64) {
        float4 a = make_float4(0.f, 0.f, 0.f, 0.f);
        #pragma unroll
        for (int j = 0; j < 16; j++) {
            float w = att_s[j];
            float4 vv = ((const float4*)(g_v + ((size_t)b*NN + nbs[j])*256))[t];
            a.x = fmaf(w, vv.x, a.x); a.y = fmaf(w, vv.y, a.y);
            a.z = fmaf(w, vv.z, a.z); a.w = fmaf(w, vv.w, a.w);
        }
        ((float4*)(g_agg + node*256))[t] = a;
    }
}

// ---------------- TV regularizer ----------------
__global__ void zero_red_kernel() { g_red[0] = 0.f; g_red[1] = 0.f; }

__global__ void tv_kernel() {
    int i = blockIdx.x*blockDim.x + threadIdx.x;   // 0..65535
    int p = i & (NN-1);
    int r = p >> 7, cc = p & (NW-1);
    float a = g_Anorm[i];
    float dy = (r  < NH-1) ? fabsf(g_Anorm[i+NW] - a) : 0.f;
    float dx = (cc < NW-1) ? fabsf(g_Anorm[i+1]  - a) : 0.f;
    #pragma unroll
    for (int off = 16; off; off >>= 1) {
        dy += __shfl_xor_sync(0xffffffffu, dy, off);
        dx += __shfl_xor_sync(0xffffffffu, dx, off);
    }
    if ((threadIdx.x & 31) == 0) {
        atomicAdd(&g_red[0], dy);
        atomicAdd(&g_red[1], dx);
    }
}

__global__ void fin_kernel(float* out, int pos) {
    out[pos] = 0.001f * (g_red[1]*(1.0f/65024.f) + g_red[0]*(1.0f/65024.f));
}

// ---------------- launch ----------------
extern "C" void kernel_launch(void* const* d_in, const int* in_sizes, int n_in,
                              void* d_out, int out_size)
{
    (void)in_sizes; (void)n_in;
    const float* z   = (const float*)d_in[0];
    const float* S   = (const float*)d_in[1];
    const float* rel = (const float*)d_in[2];
    const float* geod= (const float*)d_in[3];
    const int*   idx = (const int*)  d_in[4];
    const float* Wq  = (const float*)d_in[5];
    const float* bq  = (const float*)d_in[6];
    const float* Wk  = (const float*)d_in[7];
    const float* bk  = (const float*)d_in[8];
    const float* Wv  = (const float*)d_in[9];
    const float* bv  = (const float*)d_in[10];
    const float* Wo  = (const float*)d_in[11];
    const float* bo  = (const float*)d_in[12];
    const float* lng = (const float*)d_in[13];
    const float* lnb = (const float*)d_in[14];
    const float* Ws1 = (const float*)d_in[15];
    const float* bs1 = (const float*)d_in[16];
    const float* Ws2 = (const float*)d_in[17];
    const float* bs2 = (const float*)d_in[18];
    const float* Wzg = (const float*)d_in[19];
    const float* bzg = (const float*)d_in[20];
    const float* Wph = (const float*)d_in[21];
    const float* bph = (const float*)d_in[22];
    const float* Wsg = (const float*)d_in[23];
    const float* bsg = (const float*)d_in[24];
    float* out = (float*)d_out;

    float *pq, *pk, *pv, *pagg;
    cudaGetSymbolAddress((void**)&pq,   g_q);
    cudaGetSymbolAddress((void**)&pk,   g_k);
    cudaGetSymbolAddress((void**)&pv,   g_v);
    cudaGetSymbolAddress((void**)&pagg, g_agg);

    dim3 gg(MTOT/64);
    sgemm_k<<<gg, 256>>>(z, Wq, bq, pq, nullptr, nullptr, nullptr, 0);
    sgemm_k<<<gg, 256>>>(z, Wk, bk, pk, nullptr, nullptr, nullptr, 0);
    sgemm_k<<<gg, 256>>>(z, Wv, bv, pv, nullptr, nullptr, nullptr, 0);

    param_kernel<<<MTOT/256, 256>>>(z, S, Wzg, bzg, Ws1, bs1, Ws2, bs2,
                                    Wph, bph, Wsg, bsg);

    dim3 ga(NN, NB);
    attn_kernel<<<ga, 256>>>(S, rel, geod, idx);

    sgemm_k<<<gg, 256>>>(pagg, Wo, bo, out, z, lng, lnb, 1);

    zero_red_kernel<<<1, 1>>>();
    tv_kernel<<<256, 256>>>();
    fin_kernel<<<1, 1>>>(out, out_size - 1);
}